// round 14
// baseline (speedup 1.0000x reference)
#include <cuda_runtime.h>
#include <cuda_fp16.h>
#include <cstdint>

// ============================================================================
// GroupedMultiQueryAttention — full algebraic reduction, low-rank factored.
//   out[g] = X[g] @ Wv[g] @ Weff[g]   (attention = 64*v; Weff folds Wo)
// Round 14 (base = R12, best known 146.1us):
//   GEMM-a: 64x128 tile, 3 CTAs/SM (24 warps), 1024 CTAs — fixes the 1.73-wave
//           tail + raises occupancy. Register-convert X path kept.
//   GEMM-b: unchanged from R12.
// ============================================================================

#define NG    8
#define NEMB  1024
#define KVDIM 256
#define MROWS 4096
#define NRAT  4
#define NHD   64

// ---------------- static device scratch -------------------------------------
__device__ __half g_wt  [NG * NEMB * KVDIM];   // WeffT fp16 [g][o=1024][c=256]
__device__ __half g_wvt [NG * KVDIM * NEMB];   // WvT  fp16 [g][c=256][i=1024]
__device__ __half g_y   [NG * MROWS * KVDIM];  // Y fp16    [g][m][c]

// ---------------- PTX helpers ------------------------------------------------
__device__ __forceinline__ uint32_t smem_u32(const void* p) {
    uint32_t a;
    asm("{ .reg .u64 t; cvta.to.shared.u64 t, %1; cvt.u32.u64 %0, t; }" : "=r"(a) : "l"(p));
    return a;
}
__device__ __forceinline__ void cp16(uint32_t dst, const void* src) {
    asm volatile("cp.async.cg.shared.global [%0], [%1], 16;" :: "r"(dst), "l"(src));
}
#define CP_COMMIT() asm volatile("cp.async.commit_group;" ::: "memory")
#define CP_WAIT(n)  asm volatile("cp.async.wait_group %0;" :: "n"(n) : "memory")

__device__ __forceinline__ void ldsm_x4(uint32_t* r, uint32_t addr) {
    asm volatile("ldmatrix.sync.aligned.m8n8.x4.shared.b16 {%0,%1,%2,%3}, [%4];"
                 : "=r"(r[0]), "=r"(r[1]), "=r"(r[2]), "=r"(r[3]) : "r"(addr));
}
__device__ __forceinline__ void mma_fp16(float* d, const uint32_t* a, const uint32_t* b) {
    asm volatile("mma.sync.aligned.m16n8k16.row.col.f32.f16.f16.f32 "
                 "{%0,%1,%2,%3}, {%4,%5,%6,%7}, {%8,%9}, {%0,%1,%2,%3};"
                 : "+f"(d[0]), "+f"(d[1]), "+f"(d[2]), "+f"(d[3])
                 : "r"(a[0]), "r"(a[1]), "r"(a[2]), "r"(a[3]), "r"(b[0]), "r"(b[1]));
}
__device__ __forceinline__ void ldg128(float* v, const float* p) {
    asm volatile("ld.global.v4.f32 {%0,%1,%2,%3}, [%4];"
                 : "=f"(v[0]), "=f"(v[1]), "=f"(v[2]), "=f"(v[3]) : "l"(p));
}

// ============================================================================
// GEMM-a: Y[64-row,128-col block] = fp16(X) @ WvT^T  (K=1024)
// BM=64, BN=128, BK=32; warp tile 32x32 (2m x 4n warps).
// 3-stage fp16-A ring (LDG->cvt->STS) + 3-stage cp.async B ring. 3 CTAs/SM.
// ============================================================================
#define XBK 32
#define XLDT 40
#define XA_STAGE (64 * XLDT * 2)              // 5120
#define XB_STAGE (128 * XLDT * 2)             // 10240
#define XOFF_B (3 * XA_STAGE)                 // 15360
#define XSMEM_TOT (XOFF_B + 3 * XB_STAGE)     // 46080

__global__ void __launch_bounds__(256, 3)
gemm_xa_kernel(const float* __restrict__ X, const __half* __restrict__ B,
               __half* __restrict__ Y, int K, int Mg, int Ntot) {
    extern __shared__ char smem[];
    const uint32_t sbase = smem_u32(smem);
    const int tid = threadIdx.x, wid = tid >> 5, lid = tid & 31;
    const int g = blockIdx.z;
    const int mBase = blockIdx.y * 64, nBase = blockIdx.x * 128;

    const float*  a0 = X + (size_t)g * Mg * K + (size_t)mBase * K;
    const __half* b0 = B + (size_t)g * Ntot * K + (size_t)nBase * K;
    __half* c = Y + (size_t)g * Mg * Ntot + (size_t)mBase * Ntot + nBase;

    // 2 (m) x 4 (n) warps; warp tile 32 x 32
    const int wm = (wid >> 2) * 32, wn = (wid & 3) * 32;
    const int lr = lid & 7, ls = lid >> 3;
    const uint32_t aRow = (uint32_t)((ls & 1) * 8 + lr);
    const uint32_t aK   = (uint32_t)((ls >> 1) * 8);
    const uint32_t bRow = (uint32_t)(((lid >> 4) & 1) * 8 + lr);
    const uint32_t bK   = (uint32_t)(((lid >> 3) & 1) * 8);

    // A LDG mapping: 2 groups/thread (64 rows x 8 chunks = 512)
    const float* aptr[2];
    uint32_t stsOff[2];
#pragma unroll
    for (int j = 0; j < 2; j++) {
        int idx = tid + j * 256, row = idx >> 3, c4 = idx & 7;
        aptr[j] = a0 + (size_t)row * K + c4 * 4;
        stsOff[j] = (uint32_t)(row * XLDT + c4 * 4) * 2;
    }

    auto cpB = [&](int s, int k0) {
#pragma unroll
        for (int i = 0; i < 2; i++) {
            int op = tid + i * 256, row = op >> 2, cc = op & 3;
            cp16(sbase + XOFF_B + (uint32_t)s * XB_STAGE
                     + (uint32_t)(row * XLDT + cc * 8) * 2,
                 b0 + (size_t)row * K + k0 + cc * 8);
        }
    };
    float rA[8];
    auto ldgA = [&](int k0) {
#pragma unroll
        for (int j = 0; j < 2; j++) ldg128(rA + j * 4, aptr[j] + k0);
    };
    auto stsA = [&](int s) {
        const uint32_t st = sbase + (uint32_t)s * XA_STAGE;
#pragma unroll
        for (int j = 0; j < 2; j++) {
            __half2 p0 = __floats2half2_rn(rA[j*4+0], rA[j*4+1]);
            __half2 p1 = __floats2half2_rn(rA[j*4+2], rA[j*4+3]);
            asm volatile("st.shared.v2.b32 [%0], {%1,%2};"
                         :: "r"(st + stsOff[j]),
                            "r"(*(uint32_t*)&p0), "r"(*(uint32_t*)&p1));
        }
    };

    float acc[2][4][4];
#pragma unroll
    for (int mt = 0; mt < 2; mt++)
#pragma unroll
        for (int nt = 0; nt < 4; nt++)
#pragma unroll
            for (int q = 0; q < 4; q++) acc[mt][nt][q] = 0.f;

    const int nk = K / XBK;                    // 32
    // prologue (R12 structure)
    ldgA(0);
    stsA(0);
    cpB(0, 0);  CP_COMMIT();
    ldgA(XBK);
    cpB(1, XBK); CP_COMMIT();

    for (int it = 0; it < nk; ++it) {
        CP_WAIT(1);
        __syncthreads();
        if (it + 2 < nk) {
            stsA((it + 1) % 3);                // publish chunk it+1
            ldgA((it + 2) * XBK);              // prefetch chunk it+2
            cpB((it + 2) % 3, (it + 2) * XBK);
        } else if (it + 1 < nk) {
            stsA((it + 1) % 3);
        }
        CP_COMMIT();

        const uint32_t ast = sbase + (uint32_t)(it % 3) * XA_STAGE;
        const uint32_t bst = sbase + XOFF_B + (uint32_t)(it % 3) * XB_STAGE;
#pragma unroll
        for (int kk = 0; kk < XBK; kk += 16) {
            uint32_t bf[4][2];
#pragma unroll
            for (int p = 0; p < 2; p++) {
                uint32_t r[4];
                uint32_t ro = (uint32_t)((wn + p * 16 + bRow) * XLDT + kk + bK) * 2;
                ldsm_x4(r, bst + ro);
                bf[p * 2 + 0][0] = r[0]; bf[p * 2 + 0][1] = r[1];
                bf[p * 2 + 1][0] = r[2]; bf[p * 2 + 1][1] = r[3];
            }
#pragma unroll
            for (int mt = 0; mt < 2; mt++) {
                uint32_t a[4];
                uint32_t ro = (uint32_t)((wm + mt * 16 + aRow) * XLDT + kk + aK) * 2;
                ldsm_x4(a, ast + ro);
#pragma unroll
                for (int nt = 0; nt < 4; nt++)
                    mma_fp16(acc[mt][nt], a, bf[nt]);
            }
        }
    }

    const int er = lid >> 2, ec = (lid & 3) * 2;
#pragma unroll
    for (int mt = 0; mt < 2; mt++)
#pragma unroll
        for (int nt = 0; nt < 4; nt++) {
            int row = wm + mt * 16 + er, col = wn + nt * 8 + ec;
            __half2 v01 = __floats2half2_rn(acc[mt][nt][0], acc[mt][nt][1]);
            __half2 v23 = __floats2half2_rn(acc[mt][nt][2], acc[mt][nt][3]);
            *(uint32_t*)&c[(size_t)row * Ntot + col] = *(uint32_t*)&v01;
            *(uint32_t*)&c[(size_t)(row + 8) * Ntot + col] = *(uint32_t*)&v23;
        }
}

// ============================================================================
// GEMM-b (unchanged R12): out[128,128] = Y[128,256] @ WeffT^T — BK=64,
// 3-stage ring, single barrier per iteration.
// ============================================================================
#define BM 128
#define BN 128
#define BK 64
#define LDT 72
#define TILE_BYTES (128 * LDT * 2)            // 18432
#define OFF_B TILE_BYTES
#define STAGE (TILE_BYTES * 2)                // 36864
#define NST 3
#define SMEM_TOT (NST * STAGE)                // 110592

template <typename T>
__device__ __forceinline__ void load_tile(uint32_t dst, const T* __restrict__ src,
                                          int k0, int K, int tid) {
#pragma unroll
    for (int i = 0; i < 4; i++) {
        int op = tid + i * 256;
        int row = op >> 3, c = op & 7;
        uint32_t off = (uint32_t)(row * LDT + c * 8) * 2;
        cp16(dst + off, src + (size_t)row * K + k0 + c * 8);
    }
}

__global__ void __launch_bounds__(256, 2)
gemm_b_kernel(const __half* __restrict__ A, const __half* __restrict__ B,
              float* __restrict__ C, int K, int Mg, int Ntot) {
    extern __shared__ char smem[];
    const uint32_t sbase = smem_u32(smem);
    const int tid = threadIdx.x, wid = tid >> 5, lid = tid & 31;
    const int g = blockIdx.z;
    const int mBase = blockIdx.y * BM, nBase = blockIdx.x * BN;

    const __half* a0 = A + (size_t)g * Mg * K + (size_t)mBase * K;
    const __half* b0 = B + (size_t)g * Ntot * K + (size_t)nBase * K;
    float* c = C + (size_t)g * Mg * Ntot + (size_t)mBase * Ntot + nBase;

    const int wm = (wid >> 2) * 64, wn = (wid & 3) * 32;
    const int lr = lid & 7, ls = lid >> 3;
    const uint32_t aRow = (uint32_t)((ls & 1) * 8 + lr);
    const uint32_t aK   = (uint32_t)((ls >> 1) * 8);
    const uint32_t bRow = (uint32_t)(((lid >> 4) & 1) * 8 + lr);
    const uint32_t bK   = (uint32_t)(((lid >> 3) & 1) * 8);

    float acc[4][4][4];
#pragma unroll
    for (int mt = 0; mt < 4; mt++)
#pragma unroll
        for (int nt = 0; nt < 4; nt++)
#pragma unroll
            for (int q = 0; q < 4; q++) acc[mt][nt][q] = 0.f;

    const int nk = K / BK;                    // 4
#pragma unroll
    for (int p = 0; p < 2; p++) {
        const uint32_t st = sbase + (uint32_t)p * STAGE;
        load_tile(st,         a0, p * BK, K, tid);
        load_tile(st + OFF_B, b0, p * BK, K, tid);
        CP_COMMIT();
    }

    for (int it = 0; it < nk; ++it) {
        CP_WAIT(1);
        __syncthreads();
        if (it + 2 < nk) {
            const uint32_t st2 = sbase + (uint32_t)((it + 2) % NST) * STAGE;
            load_tile(st2,         a0, (it + 2) * BK, K, tid);
            load_tile(st2 + OFF_B, b0, (it + 2) * BK, K, tid);
        }
        CP_COMMIT();

        const uint32_t st = sbase + (uint32_t)(it % NST) * STAGE;
#pragma unroll
        for (int kk = 0; kk < BK; kk += 16) {
            uint32_t bf[4][2];
#pragma unroll
            for (int p = 0; p < 2; p++) {
                uint32_t r[4];
                uint32_t ro = (uint32_t)((wn + p * 16 + bRow) * LDT + kk + bK) * 2;
                ldsm_x4(r, st + OFF_B + ro);
                bf[p * 2 + 0][0] = r[0]; bf[p * 2 + 0][1] = r[1];
                bf[p * 2 + 1][0] = r[2]; bf[p * 2 + 1][1] = r[3];
            }
#pragma unroll
            for (int mt = 0; mt < 4; mt++) {
                uint32_t a[4];
                uint32_t ro = (uint32_t)((wm + mt * 16 + aRow) * LDT + kk + aK) * 2;
                ldsm_x4(a, st + ro);
#pragma unroll
                for (int nt = 0; nt < 4; nt++)
                    mma_fp16(acc[mt][nt], a, bf[nt]);
            }
        }
    }

    const int er = lid >> 2, ec = (lid & 3) * 2;
#pragma unroll
    for (int mt = 0; mt < 4; mt++)
#pragma unroll
        for (int nt = 0; nt < 4; nt++) {
            int row = wm + mt * 16 + er, col = wn + nt * 8 + ec;
            *(float2*)&c[(size_t)row * Ntot + col] =
                make_float2(acc[mt][nt][0], acc[mt][nt][1]);
            *(float2*)&c[(size_t)(row + 8) * Ntot + col] =
                make_float2(acc[mt][nt][2], acc[mt][nt][3]);
        }
}

// ---------------- helper kernels --------------------------------------------
__global__ void fold_transpose_kernel(const float* __restrict__ Wo,
                                      __half* __restrict__ out) {
    __shared__ float t[32][33];
    const int g = blockIdx.z;
    const int oB = blockIdx.x * 32;
    const int cB = blockIdx.y * 32;
    const int tx = threadIdx.x, ty = threadIdx.y;   // 32 x 8
    const float* wo = Wo + (size_t)g * NEMB * NEMB;
#pragma unroll
    for (int j = 0; j < 4; j++) {
        int cc = cB + ty + j * 8;
        int kv = cc >> 6, d = cc & 63;
        int o = oB + tx;
        float s = 0.f;
#pragma unroll
        for (int r = 0; r < NRAT; r++)
            s += wo[(size_t)((kv * NRAT + r) * NHD + d) * NEMB + o];
        t[ty + j * 8][tx] = 64.0f * s;
    }
    __syncthreads();
    __half* O = out + (size_t)g * NEMB * KVDIM;
#pragma unroll
    for (int j = 0; j < 4; j++) {
        float x = t[tx][ty + j * 8];
        O[(size_t)(oB + ty + j * 8) * KVDIM + cB + tx] = __float2half_rn(x);
    }
}

__global__ void transpose_half_kernel(const float* __restrict__ in,
                                      __half* __restrict__ out, int R, int Cc) {
    __shared__ float t[32][33];
    const int g = blockIdx.z;
    const int cB = blockIdx.x * 32, rB = blockIdx.y * 32;
    const int tx = threadIdx.x, ty = threadIdx.y;
#pragma unroll
    for (int j = 0; j < 4; j++)
        t[ty + j * 8][tx] = in[(size_t)g * R * Cc + (size_t)(rB + ty + j * 8) * Cc + cB + tx];
    __syncthreads();
    __half* O = out + (size_t)g * R * Cc;
#pragma unroll
    for (int j = 0; j < 4; j++) {
        float x = t[tx][ty + j * 8];
        O[(size_t)(cB + ty + j * 8) * R + rB + tx] = __float2half_rn(x);
    }
}

// ---------------- launch -----------------------------------------------------
extern "C" void kernel_launch(void* const* d_in, const int* in_sizes, int n_in,
                              void* d_out, int out_size) {
    const float* tensor = (const float*)d_in[0];
    const float* Wv = (const float*)d_in[3];
    const float* Wo = (const float*)d_in[4];
    float* out = (float*)d_out;

    cudaFuncSetAttribute(gemm_xa_kernel,
                         cudaFuncAttributeMaxDynamicSharedMemorySize, XSMEM_TOT);
    cudaFuncSetAttribute(gemm_b_kernel,
                         cudaFuncAttributeMaxDynamicSharedMemorySize, SMEM_TOT);

    __half *wt, *wvt, *y;
    cudaGetSymbolAddress((void**)&wt,  g_wt);
    cudaGetSymbolAddress((void**)&wvt, g_wvt);
    cudaGetSymbolAddress((void**)&y,   g_y);

    // 1. fold+transpose: Wo -> WeffT fp16 [g][1024][256]
    {
        dim3 grid(NEMB / 32, KVDIM / 32, NG);
        fold_transpose_kernel<<<grid, dim3(32, 8)>>>(Wo, wt);
    }
    // 2. Wv [1024][256] -> WvT fp16 [256][1024]
    {
        dim3 grid(KVDIM / 32, NEMB / 32, NG);
        transpose_half_kernel<<<grid, dim3(32, 8)>>>(Wv, wvt, NEMB, KVDIM);
    }
    // 3. GEMM-a: Y = fp16(X) @ WvT^T  (K=1024, N=256) — 1024 CTAs, 3 CTAs/SM
    {
        dim3 grid(KVDIM / 128, MROWS / 64, NG);    // (2, 64, 8)
        gemm_xa_kernel<<<grid, 256, XSMEM_TOT>>>(tensor, wvt, y,
                                                 NEMB, MROWS, KVDIM);
    }
    // 4. GEMM-b: out = Y @ WeffT^T  (K=256, N=1024, fp32 out)
    {
        dim3 grid(NEMB / BN, MROWS / BM, NG);      // (8, 32, 8)
        gemm_b_kernel<<<grid, 256, SMEM_TOT>>>(y, wt, out,
                                               KVDIM, MROWS, NEMB);
    }
}

// round 15
// speedup vs baseline: 1.5200x; 1.5200x over previous
#include <cuda_runtime.h>
#include <cuda_fp16.h>
#include <cstdint>

// ============================================================================
// GroupedMultiQueryAttention — full algebraic reduction, low-rank factored.
//   out[g] = X[g] @ Wv[g] @ Weff[g]   (attention = 64*v; Weff folds Wo)
// FINAL (= Round 12, measured 146.1us / rel_err 4.1e-4):
//   GEMM-a: X fp32 -> registers (pinned LDG) -> fp16 STS. No fp32 smem, no
//           separate convert pass. Single barrier/iter: [wait][sync][produce][MMA].
//   GEMM-b: 128x128 BK=64 3-stage ring, single barrier/iter.
// R11/R13/R14 established this as the local optimum: bigger-N tiles, phase
// fusion, and smaller-M/higher-occupancy variants all regressed.
// ============================================================================

#define NG    8
#define NEMB  1024
#define KVDIM 256
#define MROWS 4096
#define NRAT  4
#define NHD   64

// ---------------- static device scratch -------------------------------------
__device__ __half g_wt  [NG * NEMB * KVDIM];   // WeffT fp16 [g][o=1024][c=256]
__device__ __half g_wvt [NG * KVDIM * NEMB];   // WvT  fp16 [g][c=256][i=1024]
__device__ __half g_y   [NG * MROWS * KVDIM];  // Y fp16    [g][m][c]

// ---------------- PTX helpers ------------------------------------------------
__device__ __forceinline__ uint32_t smem_u32(const void* p) {
    uint32_t a;
    asm("{ .reg .u64 t; cvta.to.shared.u64 t, %1; cvt.u32.u64 %0, t; }" : "=r"(a) : "l"(p));
    return a;
}
__device__ __forceinline__ void cp16(uint32_t dst, const void* src) {
    asm volatile("cp.async.cg.shared.global [%0], [%1], 16;" :: "r"(dst), "l"(src));
}
#define CP_COMMIT() asm volatile("cp.async.commit_group;" ::: "memory")
#define CP_WAIT(n)  asm volatile("cp.async.wait_group %0;" :: "n"(n) : "memory")

__device__ __forceinline__ void ldsm_x4(uint32_t* r, uint32_t addr) {
    asm volatile("ldmatrix.sync.aligned.m8n8.x4.shared.b16 {%0,%1,%2,%3}, [%4];"
                 : "=r"(r[0]), "=r"(r[1]), "=r"(r[2]), "=r"(r[3]) : "r"(addr));
}
__device__ __forceinline__ void mma_fp16(float* d, const uint32_t* a, const uint32_t* b) {
    asm volatile("mma.sync.aligned.m16n8k16.row.col.f32.f16.f16.f32 "
                 "{%0,%1,%2,%3}, {%4,%5,%6,%7}, {%8,%9}, {%0,%1,%2,%3};"
                 : "+f"(d[0]), "+f"(d[1]), "+f"(d[2]), "+f"(d[3])
                 : "r"(a[0]), "r"(a[1]), "r"(a[2]), "r"(a[3]), "r"(b[0]), "r"(b[1]));
}
__device__ __forceinline__ void ldg128(float* v, const float* p) {
    asm volatile("ld.global.v4.f32 {%0,%1,%2,%3}, [%4];"
                 : "=f"(v[0]), "=f"(v[1]), "=f"(v[2]), "=f"(v[3]) : "l"(p));
}

// ============================================================================
// GEMM-a: Y[128,128-block] = fp16(X) @ WvT^T  (K=1024), register-convert path.
// BK=32, 3-stage fp16-A ring (filled by LDG->cvt->STS) + 3-stage cp.async B.
// ============================================================================
#define XBK 32
#define XLDT 40
#define XSTAGE (128 * XLDT * 2)               // 10240
#define XOFF_B (3 * XSTAGE)                   // 30720
#define XSMEM_TOT (XOFF_B + 3 * XSTAGE)       // 61440

__global__ void __launch_bounds__(256, 2)
gemm_xa_kernel(const float* __restrict__ X, const __half* __restrict__ B,
               __half* __restrict__ Y, int K, int Mg, int Ntot) {
    extern __shared__ char smem[];
    const uint32_t sbase = smem_u32(smem);
    const int tid = threadIdx.x, wid = tid >> 5, lid = tid & 31;
    const int g = blockIdx.z;
    const int mBase = blockIdx.y * 128, nBase = blockIdx.x * 128;

    const float*  a0 = X + (size_t)g * Mg * K + (size_t)mBase * K;
    const __half* b0 = B + (size_t)g * Ntot * K + (size_t)nBase * K;
    __half* c = Y + (size_t)g * Mg * Ntot + (size_t)mBase * Ntot + nBase;

    const int wm = (wid >> 2) * 64, wn = (wid & 3) * 32;
    const int lr = lid & 7, ls = lid >> 3;
    const uint32_t aRow = (uint32_t)((ls & 1) * 8 + lr);
    const uint32_t aK   = (uint32_t)((ls >> 1) * 8);
    const uint32_t bRow = (uint32_t)(((lid >> 4) & 1) * 8 + lr);
    const uint32_t bK   = (uint32_t)(((lid >> 3) & 1) * 8);

    // A-LDG mapping: 4 groups/thread, idx = tid + j*256 -> row=idx>>3, c4=idx&7
    const float* aptr[4];
    uint32_t stsOff[4];
#pragma unroll
    for (int j = 0; j < 4; j++) {
        int idx = tid + j * 256, row = idx >> 3, c4 = idx & 7;
        aptr[j] = a0 + (size_t)row * K + c4 * 4;
        stsOff[j] = (uint32_t)(row * XLDT + c4 * 4) * 2;
    }

    auto cpB = [&](int s, int k0) {
#pragma unroll
        for (int i = 0; i < 2; i++) {
            int op = tid + i * 256, row = op >> 2, cc = op & 3;
            cp16(sbase + XOFF_B + (uint32_t)s * XSTAGE
                     + (uint32_t)(row * XLDT + cc * 8) * 2,
                 b0 + (size_t)row * K + k0 + cc * 8);
        }
    };
    auto ldgA = [&](float* rA, int k0) {
#pragma unroll
        for (int j = 0; j < 4; j++) ldg128(rA + j * 4, aptr[j] + k0);
    };
    auto stsA = [&](const float* rA, int s) {
        const uint32_t st = sbase + (uint32_t)s * XSTAGE;
#pragma unroll
        for (int j = 0; j < 4; j++) {
            __half2 p0 = __floats2half2_rn(rA[j*4+0], rA[j*4+1]);
            __half2 p1 = __floats2half2_rn(rA[j*4+2], rA[j*4+3]);
            asm volatile("st.shared.v2.b32 [%0], {%1,%2};"
                         :: "r"(st + stsOff[j]),
                            "r"(*(uint32_t*)&p0), "r"(*(uint32_t*)&p1));
        }
    };

    float acc[4][4][4];
#pragma unroll
    for (int mt = 0; mt < 4; mt++)
#pragma unroll
        for (int nt = 0; nt < 4; nt++)
#pragma unroll
            for (int q = 0; q < 4; q++) acc[mt][nt][q] = 0.f;

    const int nk = K / XBK;                    // 32
    float rA[16];
    // prologue: chunk0 -> stage0 (regs->sts), B0, B1; chunk1 -> regs
    ldgA(rA, 0);
    stsA(rA, 0);
    cpB(0, 0);  CP_COMMIT();
    ldgA(rA, XBK);
    cpB(1, XBK); CP_COMMIT();

    for (int it = 0; it < nk; ++it) {
        CP_WAIT(1);
        __syncthreads();
        if (it + 2 < nk) {
            stsA(rA, (it + 1) % 3);            // publish chunk it+1
            ldgA(rA, (it + 2) * XBK);          // prefetch chunk it+2
            cpB((it + 2) % 3, (it + 2) * XBK);
        } else if (it + 1 < nk) {
            stsA(rA, (it + 1) % 3);
        }
        CP_COMMIT();

        const uint32_t ast = sbase + (uint32_t)(it % 3) * XSTAGE;
        const uint32_t bst = sbase + XOFF_B + (uint32_t)(it % 3) * XSTAGE;
#pragma unroll
        for (int kk = 0; kk < XBK; kk += 16) {
            uint32_t bf[4][2];
#pragma unroll
            for (int p = 0; p < 2; p++) {
                uint32_t r[4];
                uint32_t ro = (uint32_t)((wn + p * 16 + bRow) * XLDT + kk + bK) * 2;
                ldsm_x4(r, bst + ro);
                bf[p * 2 + 0][0] = r[0]; bf[p * 2 + 0][1] = r[1];
                bf[p * 2 + 1][0] = r[2]; bf[p * 2 + 1][1] = r[3];
            }
#pragma unroll
            for (int mt = 0; mt < 4; mt++) {
                uint32_t a[4];
                uint32_t ro = (uint32_t)((wm + mt * 16 + aRow) * XLDT + kk + aK) * 2;
                ldsm_x4(a, ast + ro);
#pragma unroll
                for (int nt = 0; nt < 4; nt++)
                    mma_fp16(acc[mt][nt], a, bf[nt]);
            }
        }
    }

    const int er = lid >> 2, ec = (lid & 3) * 2;
#pragma unroll
    for (int mt = 0; mt < 4; mt++)
#pragma unroll
        for (int nt = 0; nt < 4; nt++) {
            int row = wm + mt * 16 + er, col = wn + nt * 8 + ec;
            __half2 v01 = __floats2half2_rn(acc[mt][nt][0], acc[mt][nt][1]);
            __half2 v23 = __floats2half2_rn(acc[mt][nt][2], acc[mt][nt][3]);
            *(uint32_t*)&c[(size_t)row * Ntot + col] = *(uint32_t*)&v01;
            *(uint32_t*)&c[(size_t)(row + 8) * Ntot + col] = *(uint32_t*)&v23;
        }
}

// ============================================================================
// GEMM-b: out[128,128] = Y[128,256] @ WeffT^T — BK=64, 3-stage ring,
// single barrier per iteration.
// ============================================================================
#define BM 128
#define BN 128
#define BK 64
#define LDT 72
#define TILE_BYTES (128 * LDT * 2)            // 18432
#define OFF_B TILE_BYTES
#define STAGE (TILE_BYTES * 2)                // 36864
#define NST 3
#define SMEM_TOT (NST * STAGE)                // 110592

template <typename T>
__device__ __forceinline__ void load_tile(uint32_t dst, const T* __restrict__ src,
                                          int k0, int K, int tid) {
#pragma unroll
    for (int i = 0; i < 4; i++) {
        int op = tid + i * 256;
        int row = op >> 3, c = op & 7;
        uint32_t off = (uint32_t)(row * LDT + c * 8) * 2;
        cp16(dst + off, src + (size_t)row * K + k0 + c * 8);
    }
}

__global__ void __launch_bounds__(256, 2)
gemm_b_kernel(const __half* __restrict__ A, const __half* __restrict__ B,
              float* __restrict__ C, int K, int Mg, int Ntot) {
    extern __shared__ char smem[];
    const uint32_t sbase = smem_u32(smem);
    const int tid = threadIdx.x, wid = tid >> 5, lid = tid & 31;
    const int g = blockIdx.z;
    const int mBase = blockIdx.y * BM, nBase = blockIdx.x * BN;

    const __half* a0 = A + (size_t)g * Mg * K + (size_t)mBase * K;
    const __half* b0 = B + (size_t)g * Ntot * K + (size_t)nBase * K;
    float* c = C + (size_t)g * Mg * Ntot + (size_t)mBase * Ntot + nBase;

    const int wm = (wid >> 2) * 64, wn = (wid & 3) * 32;
    const int lr = lid & 7, ls = lid >> 3;
    const uint32_t aRow = (uint32_t)((ls & 1) * 8 + lr);
    const uint32_t aK   = (uint32_t)((ls >> 1) * 8);
    const uint32_t bRow = (uint32_t)(((lid >> 4) & 1) * 8 + lr);
    const uint32_t bK   = (uint32_t)(((lid >> 3) & 1) * 8);

    float acc[4][4][4];
#pragma unroll
    for (int mt = 0; mt < 4; mt++)
#pragma unroll
        for (int nt = 0; nt < 4; nt++)
#pragma unroll
            for (int q = 0; q < 4; q++) acc[mt][nt][q] = 0.f;

    const int nk = K / BK;                    // 4
    // prologue: stages 0,1
#pragma unroll
    for (int p = 0; p < 2; p++) {
        const uint32_t st = sbase + (uint32_t)p * STAGE;
        load_tile(st,         a0, p * BK, K, tid);
        load_tile(st + OFF_B, b0, p * BK, K, tid);
        CP_COMMIT();
    }

    for (int it = 0; it < nk; ++it) {
        CP_WAIT(1);
        __syncthreads();
        if (it + 2 < nk) {
            const uint32_t st2 = sbase + (uint32_t)((it + 2) % NST) * STAGE;
            load_tile(st2,         a0, (it + 2) * BK, K, tid);
            load_tile(st2 + OFF_B, b0, (it + 2) * BK, K, tid);
        }
        CP_COMMIT();

        const uint32_t st = sbase + (uint32_t)(it % NST) * STAGE;
#pragma unroll
        for (int kk = 0; kk < BK; kk += 16) {
            uint32_t bf[4][2];
#pragma unroll
            for (int p = 0; p < 2; p++) {
                uint32_t r[4];
                uint32_t ro = (uint32_t)((wn + p * 16 + bRow) * LDT + kk + bK) * 2;
                ldsm_x4(r, st + OFF_B + ro);
                bf[p * 2 + 0][0] = r[0]; bf[p * 2 + 0][1] = r[1];
                bf[p * 2 + 1][0] = r[2]; bf[p * 2 + 1][1] = r[3];
            }
#pragma unroll
            for (int mt = 0; mt < 4; mt++) {
                uint32_t a[4];
                uint32_t ro = (uint32_t)((wm + mt * 16 + aRow) * LDT + kk + aK) * 2;
                ldsm_x4(a, st + ro);
#pragma unroll
                for (int nt = 0; nt < 4; nt++)
                    mma_fp16(acc[mt][nt], a, bf[nt]);
            }
        }
    }

    const int er = lid >> 2, ec = (lid & 3) * 2;
#pragma unroll
    for (int mt = 0; mt < 4; mt++)
#pragma unroll
        for (int nt = 0; nt < 4; nt++) {
            int row = wm + mt * 16 + er, col = wn + nt * 8 + ec;
            *(float2*)&c[(size_t)row * Ntot + col] =
                make_float2(acc[mt][nt][0], acc[mt][nt][1]);
            *(float2*)&c[(size_t)(row + 8) * Ntot + col] =
                make_float2(acc[mt][nt][2], acc[mt][nt][3]);
        }
}

// ---------------- helper kernels --------------------------------------------
__global__ void fold_transpose_kernel(const float* __restrict__ Wo,
                                      __half* __restrict__ out) {
    __shared__ float t[32][33];
    const int g = blockIdx.z;
    const int oB = blockIdx.x * 32;
    const int cB = blockIdx.y * 32;
    const int tx = threadIdx.x, ty = threadIdx.y;   // 32 x 8
    const float* wo = Wo + (size_t)g * NEMB * NEMB;
#pragma unroll
    for (int j = 0; j < 4; j++) {
        int cc = cB + ty + j * 8;
        int kv = cc >> 6, d = cc & 63;
        int o = oB + tx;
        float s = 0.f;
#pragma unroll
        for (int r = 0; r < NRAT; r++)
            s += wo[(size_t)((kv * NRAT + r) * NHD + d) * NEMB + o];
        t[ty + j * 8][tx] = 64.0f * s;
    }
    __syncthreads();
    __half* O = out + (size_t)g * NEMB * KVDIM;
#pragma unroll
    for (int j = 0; j < 4; j++) {
        float x = t[tx][ty + j * 8];
        O[(size_t)(oB + ty + j * 8) * KVDIM + cB + tx] = __float2half_rn(x);
    }
}

__global__ void transpose_half_kernel(const float* __restrict__ in,
                                      __half* __restrict__ out, int R, int Cc) {
    __shared__ float t[32][33];
    const int g = blockIdx.z;
    const int cB = blockIdx.x * 32, rB = blockIdx.y * 32;
    const int tx = threadIdx.x, ty = threadIdx.y;
#pragma unroll
    for (int j = 0; j < 4; j++)
        t[ty + j * 8][tx] = in[(size_t)g * R * Cc + (size_t)(rB + ty + j * 8) * Cc + cB + tx];
    __syncthreads();
    __half* O = out + (size_t)g * R * Cc;
#pragma unroll
    for (int j = 0; j < 4; j++) {
        float x = t[tx][ty + j * 8];
        O[(size_t)(cB + ty + j * 8) * R + rB + tx] = __float2half_rn(x);
    }
}

// ---------------- launch -----------------------------------------------------
extern "C" void kernel_launch(void* const* d_in, const int* in_sizes, int n_in,
                              void* d_out, int out_size) {
    const float* tensor = (const float*)d_in[0];
    const float* Wv = (const float*)d_in[3];
    const float* Wo = (const float*)d_in[4];
    float* out = (float*)d_out;

    cudaFuncSetAttribute(gemm_xa_kernel,
                         cudaFuncAttributeMaxDynamicSharedMemorySize, XSMEM_TOT);
    cudaFuncSetAttribute(gemm_b_kernel,
                         cudaFuncAttributeMaxDynamicSharedMemorySize, SMEM_TOT);

    __half *wt, *wvt, *y;
    cudaGetSymbolAddress((void**)&wt,  g_wt);
    cudaGetSymbolAddress((void**)&wvt, g_wvt);
    cudaGetSymbolAddress((void**)&y,   g_y);

    // 1. fold+transpose: Wo -> WeffT fp16 [g][1024][256]
    {
        dim3 grid(NEMB / 32, KVDIM / 32, NG);
        fold_transpose_kernel<<<grid, dim3(32, 8)>>>(Wo, wt);
    }
    // 2. Wv [1024][256] -> WvT fp16 [256][1024]
    {
        dim3 grid(KVDIM / 32, NEMB / 32, NG);
        transpose_half_kernel<<<grid, dim3(32, 8)>>>(Wv, wvt, NEMB, KVDIM);
    }
    // 3. GEMM-a (register convert): Y = fp16(X) @ WvT^T  (K=1024, N=256)
    {
        dim3 grid(KVDIM / 128, MROWS / 128, NG);   // (2, 32, 8) = 512 CTAs
        gemm_xa_kernel<<<grid, 256, XSMEM_TOT>>>(tensor, wvt, y,
                                                 NEMB, MROWS, KVDIM);
    }
    // 4. GEMM-b: out = Y @ WeffT^T  (K=256, N=1024, fp32 out)
    {
        dim3 grid(NEMB / BN, MROWS / BM, NG);      // (8, 32, 8) = 2048 CTAs
        gemm_b_kernel<<<grid, 256, SMEM_TOT>>>(y, wt, out,
                                               KVDIM, MROWS, NEMB);
    }
}